// round 1
// baseline (speedup 1.0000x reference)
#include <cuda_runtime.h>
#include <math.h>

#define B_ 2
#define T_ 2048
#define C_ 1024
#define H_ 16
#define D_ 64
#define M_ (B_*T_)
#define SCALE_ 0.125f

// Scratch (static device globals -- no allocation)
__device__ float g_q[(size_t)B_*H_*T_*D_];
__device__ float g_k[(size_t)B_*H_*T_*D_];
__device__ float g_v[(size_t)B_*H_*T_*D_];
__device__ float g_ao[(size_t)M_*C_];

// ---------------------------------------------------------------------------
// GEMM: Y = A @ W^T   (A: [M,K] row-major, W: [N,K] row-major)  fp32 SIMT
// 128x128 block tile, BK=16, 256 threads, 8x8 microtile.
// ---------------------------------------------------------------------------

__global__ __launch_bounds__(256) void gemm_qkv(
    const float* __restrict__ x,
    const float* __restrict__ wq,
    const float* __restrict__ wk,
    const float* __restrict__ wv)
{
    __shared__ float As[16][132];
    __shared__ float Bs[16][132];

    const float* W = (blockIdx.z == 0) ? wq : (blockIdx.z == 1) ? wk : wv;
    float* out     = (blockIdx.z == 0) ? g_q : (blockIdx.z == 1) ? g_k : g_v;

    const int tid = threadIdx.x;
    const int tr = tid >> 4, tc = tid & 15;
    const float* Ab = x + (size_t)blockIdx.y * 128 * C_;
    const float* Wb = W + (size_t)blockIdx.x * 128 * C_;

    float acc[8][8];
#pragma unroll
    for (int i = 0; i < 8; i++)
#pragma unroll
        for (int j = 0; j < 8; j++) acc[i][j] = 0.f;

    for (int k0 = 0; k0 < C_; k0 += 16) {
#pragma unroll
        for (int l = 0; l < 2; l++) {
            int idx = tid + l * 256;
            int row = idx >> 2;
            int kc  = (idx & 3) << 2;
            float4 av = *(const float4*)(Ab + (size_t)row * C_ + k0 + kc);
            float4 bv = *(const float4*)(Wb + (size_t)row * C_ + k0 + kc);
            As[kc+0][row] = av.x; As[kc+1][row] = av.y;
            As[kc+2][row] = av.z; As[kc+3][row] = av.w;
            Bs[kc+0][row] = bv.x; Bs[kc+1][row] = bv.y;
            Bs[kc+2][row] = bv.z; Bs[kc+3][row] = bv.w;
        }
        __syncthreads();
#pragma unroll
        for (int k = 0; k < 16; k++) {
            float a[8], b[8];
            *(float4*)(a)   = *(const float4*)&As[k][tr*4];
            *(float4*)(a+4) = *(const float4*)&As[k][tr*4+64];
            *(float4*)(b)   = *(const float4*)&Bs[k][tc*4];
            *(float4*)(b+4) = *(const float4*)&Bs[k][tc*4+64];
#pragma unroll
            for (int i = 0; i < 8; i++)
#pragma unroll
                for (int j = 0; j < 8; j++)
                    acc[i][j] = fmaf(a[i], b[j], acc[i][j]);
        }
        __syncthreads();
    }

    // Epilogue: scatter into [B,H,T,D]
#pragma unroll
    for (int i = 0; i < 8; i++) {
        int m = blockIdx.y*128 + tr*4 + (i&3) + ((i>>2)<<6);
        int b = m >> 11;          // m / T_
        int t = m & (T_-1);
#pragma unroll
        for (int j = 0; j < 8; j++) {
            int n = blockIdx.x*128 + tc*4 + (j&3) + ((j>>2)<<6);
            int h = n >> 6, d = n & 63;
            out[(((size_t)(b*H_ + h))*T_ + t)*D_ + d] = acc[i][j];
        }
    }
}

__global__ __launch_bounds__(256) void gemm_out(
    const float* __restrict__ wo,
    float* __restrict__ out)
{
    __shared__ float As[16][132];
    __shared__ float Bs[16][132];

    const int tid = threadIdx.x;
    const int tr = tid >> 4, tc = tid & 15;
    const float* Ab = g_ao + (size_t)blockIdx.y * 128 * C_;
    const float* Wb = wo   + (size_t)blockIdx.x * 128 * C_;

    float acc[8][8];
#pragma unroll
    for (int i = 0; i < 8; i++)
#pragma unroll
        for (int j = 0; j < 8; j++) acc[i][j] = 0.f;

    for (int k0 = 0; k0 < C_; k0 += 16) {
#pragma unroll
        for (int l = 0; l < 2; l++) {
            int idx = tid + l * 256;
            int row = idx >> 2;
            int kc  = (idx & 3) << 2;
            float4 av = *(const float4*)(Ab + (size_t)row * C_ + k0 + kc);
            float4 bv = *(const float4*)(Wb + (size_t)row * C_ + k0 + kc);
            As[kc+0][row] = av.x; As[kc+1][row] = av.y;
            As[kc+2][row] = av.z; As[kc+3][row] = av.w;
            Bs[kc+0][row] = bv.x; Bs[kc+1][row] = bv.y;
            Bs[kc+2][row] = bv.z; Bs[kc+3][row] = bv.w;
        }
        __syncthreads();
#pragma unroll
        for (int k = 0; k < 16; k++) {
            float a[8], b[8];
            *(float4*)(a)   = *(const float4*)&As[k][tr*4];
            *(float4*)(a+4) = *(const float4*)&As[k][tr*4+64];
            *(float4*)(b)   = *(const float4*)&Bs[k][tc*4];
            *(float4*)(b+4) = *(const float4*)&Bs[k][tc*4+64];
#pragma unroll
            for (int i = 0; i < 8; i++)
#pragma unroll
                for (int j = 0; j < 8; j++)
                    acc[i][j] = fmaf(a[i], b[j], acc[i][j]);
        }
        __syncthreads();
    }

#pragma unroll
    for (int i = 0; i < 8; i++) {
        int m = blockIdx.y*128 + tr*4 + (i&3) + ((i>>2)<<6);
#pragma unroll
        for (int j = 0; j < 8; j++) {
            int n = blockIdx.x*128 + tc*4 + (j&3) + ((j>>2)<<6);
            out[(size_t)m*C_ + n] = acc[i][j];
        }
    }
}

// ---------------------------------------------------------------------------
// Flash attention: 128 queries x 128 keys per tile, online softmax.
// One block (256 threads) per (bh, q-tile). Causal.
// ---------------------------------------------------------------------------

#define QS_OFF 0
#define KS_OFF (64*132)
#define VS_OFF (KS_OFF + 64*132)
#define PS_OFF (VS_OFF + 128*68)
#define ATT_SMEM_FLOATS (PS_OFF + 128*128)
#define ATT_SMEM (ATT_SMEM_FLOATS * 4)

__global__ __launch_bounds__(256, 1) void attn_kernel()
{
    extern __shared__ float sm[];
    float* Qs = sm + QS_OFF;   // [64 d][132] transposed: Qs[d][q]
    float* Ks = sm + KS_OFF;   // [64 d][132] transposed: Ks[d][kcol]
    float* Vs = sm + VS_OFF;   // [128 k][68] natural:   Vs[k][d]
    float* Ps = sm + PS_OFF;   // [128 k][128 q] XOR-swizzled chunks

    const int tid = threadIdx.x;
    const int tr = tid >> 4, tc = tid & 15;
    const int bh = blockIdx.y;
    const int qt = 15 - (int)blockIdx.x;   // heavy tiles scheduled first

    const float* Qg = g_q + ((size_t)bh*T_ + (size_t)qt*128) * D_;
    const float* Kg = g_k + (size_t)bh*T_*D_;
    const float* Vg = g_v + (size_t)bh*T_*D_;

    // Load Q tile transposed, pre-scaled by 1/sqrt(D)
#pragma unroll
    for (int l = 0; l < 8; l++) {
        int idx = tid + l*256;
        int q   = idx >> 4;
        int d0  = (idx & 15) << 2;
        float4 v = *(const float4*)(Qg + (size_t)q*D_ + d0);
        Qs[(d0+0)*132 + q] = v.x*SCALE_;
        Qs[(d0+1)*132 + q] = v.y*SCALE_;
        Qs[(d0+2)*132 + q] = v.z*SCALE_;
        Qs[(d0+3)*132 + q] = v.w*SCALE_;
    }

    float m_i[8], l_i[8], o[8][4];
#pragma unroll
    for (int i = 0; i < 8; i++) {
        m_i[i] = -INFINITY; l_i[i] = 0.f;
#pragma unroll
        for (int j = 0; j < 4; j++) o[i][j] = 0.f;
    }

    for (int kt = 0; kt <= qt; kt++) {
        __syncthreads();   // previous PV done with Vs/Ps; safe to reload K/V
#pragma unroll
        for (int l = 0; l < 8; l++) {
            int idx = tid + l*256;
            int r   = idx >> 4;
            int d0  = (idx & 15) << 2;
            size_t g = ((size_t)(kt*128 + r))*D_ + d0;
            float4 kv = *(const float4*)(Kg + g);
            Ks[(d0+0)*132 + r] = kv.x;
            Ks[(d0+1)*132 + r] = kv.y;
            Ks[(d0+2)*132 + r] = kv.z;
            Ks[(d0+3)*132 + r] = kv.w;
            float4 vv = *(const float4*)(Vg + g);
            *(float4*)&Vs[r*68 + d0] = vv;
        }
        __syncthreads();

        // S = Q K^T  (128x128, 8x8 per thread)
        float s[8][8];
#pragma unroll
        for (int i = 0; i < 8; i++)
#pragma unroll
            for (int j = 0; j < 8; j++) s[i][j] = 0.f;

#pragma unroll 4
        for (int d = 0; d < 64; d++) {
            float a[8], b[8];
            *(float4*)(a)   = *(const float4*)&Qs[d*132 + tr*4];
            *(float4*)(a+4) = *(const float4*)&Qs[d*132 + tr*4 + 64];
            *(float4*)(b)   = *(const float4*)&Ks[d*132 + tc*4];
            *(float4*)(b+4) = *(const float4*)&Ks[d*132 + tc*4 + 64];
#pragma unroll
            for (int i = 0; i < 8; i++)
#pragma unroll
                for (int j = 0; j < 8; j++)
                    s[i][j] = fmaf(a[i], b[j], s[i][j]);
        }

        if (kt == qt) {  // diagonal tile: causal mask
#pragma unroll
            for (int i = 0; i < 8; i++) {
                int ql = tr*4 + (i&3) + ((i>>2)<<6);
#pragma unroll
                for (int j = 0; j < 8; j++) {
                    int kl = tc*4 + (j&3) + ((j>>2)<<6);
                    if (kl > ql) s[i][j] = -INFINITY;
                }
            }
        }

        // Online softmax (row stats reduced over 16 lanes sharing a row group)
#pragma unroll
        for (int i = 0; i < 8; i++) {
            float mx = s[i][0];
#pragma unroll
            for (int j = 1; j < 8; j++) mx = fmaxf(mx, s[i][j]);
            mx = fmaxf(mx, __shfl_xor_sync(0xffffffffu, mx, 8));
            mx = fmaxf(mx, __shfl_xor_sync(0xffffffffu, mx, 4));
            mx = fmaxf(mx, __shfl_xor_sync(0xffffffffu, mx, 2));
            mx = fmaxf(mx, __shfl_xor_sync(0xffffffffu, mx, 1));
            float mn   = fmaxf(m_i[i], mx);
            float corr = __expf(m_i[i] - mn);
            m_i[i] = mn;
            float rs = 0.f;
#pragma unroll
            for (int j = 0; j < 8; j++) { s[i][j] = __expf(s[i][j] - mn); rs += s[i][j]; }
            rs += __shfl_xor_sync(0xffffffffu, rs, 8);
            rs += __shfl_xor_sync(0xffffffffu, rs, 4);
            rs += __shfl_xor_sync(0xffffffffu, rs, 2);
            rs += __shfl_xor_sync(0xffffffffu, rs, 1);
            l_i[i] = l_i[i]*corr + rs;
#pragma unroll
            for (int j = 0; j < 4; j++) o[i][j] *= corr;
        }

        // Write P transposed [kk][q], chunk-XOR swizzle for conflict-free access
#pragma unroll
        for (int j = 0; j < 8; j++) {
            int kk = tc*4 + (j&3) + ((j>>2)<<6);
            int sw = (kk>>2) & 7;
            float4 v0 = make_float4(s[0][j], s[1][j], s[2][j], s[3][j]);
            float4 v1 = make_float4(s[4][j], s[5][j], s[6][j], s[7][j]);
            *(float4*)&Ps[kk*128 + (( tr      ^ sw) << 2)] = v0;
            *(float4*)&Ps[kk*128 + (((tr+16) ^ sw) << 2)] = v1;
        }
        __syncthreads();

        // O += P @ V   (128x64, 8x4 per thread)
#pragma unroll 4
        for (int kk = 0; kk < 128; kk++) {
            int sw = (kk>>2) & 7;
            float4 pa = *(const float4*)&Ps[kk*128 + (( tr      ^ sw) << 2)];
            float4 pb = *(const float4*)&Ps[kk*128 + (((tr+16) ^ sw) << 2)];
            float4 vv = *(const float4*)&Vs[kk*68 + tc*4];
            float p8[8] = {pa.x,pa.y,pa.z,pa.w,pb.x,pb.y,pb.z,pb.w};
            float v4[4] = {vv.x,vv.y,vv.z,vv.w};
#pragma unroll
            for (int i = 0; i < 8; i++)
#pragma unroll
                for (int j = 0; j < 4; j++)
                    o[i][j] = fmaf(p8[i], v4[j], o[i][j]);
        }
    }

    // Normalize and write attention output to [B,T,C] scratch
    const int b = bh >> 4, h = bh & 15;
    float* Og = g_ao + ((size_t)b*T_ + (size_t)qt*128)*C_ + h*64;
#pragma unroll
    for (int i = 0; i < 8; i++) {
        int ql = tr*4 + (i&3) + ((i>>2)<<6);
        float inv = 1.f / l_i[i];
#pragma unroll
        for (int j = 0; j < 4; j++)
            Og[(size_t)ql*C_ + tc*4 + j] = o[i][j] * inv;
    }
}

// ---------------------------------------------------------------------------

extern "C" void kernel_launch(void* const* d_in, const int* in_sizes, int n_in,
                              void* d_out, int out_size)
{
    const float* x  = (const float*)d_in[0];
    // d_in[1] = causal mask (known analytically; not read)
    const float* wq = (const float*)d_in[2];
    const float* wk = (const float*)d_in[3];
    const float* wv = (const float*)d_in[4];
    const float* wo = (const float*)d_in[5];
    float* out = (float*)d_out;

    gemm_qkv<<<dim3(C_/128, M_/128, 3), 256>>>(x, wq, wk, wv);

    cudaFuncSetAttribute(attn_kernel, cudaFuncAttributeMaxDynamicSharedMemorySize, ATT_SMEM);
    attn_kernel<<<dim3(16, B_*H_), 256, ATT_SMEM>>>();

    gemm_out<<<dim3(C_/128, M_/128), 256>>>(wo, out);
}

// round 2
// speedup vs baseline: 2.4470x; 2.4470x over previous
#include <cuda_runtime.h>
#include <math.h>

#define B_ 2
#define T_ 2048
#define C_ 1024
#define H_ 16
#define D_ 64
#define M_ (B_*T_)
#define SCALE_ 0.125f

// Scratch (static device globals -- no allocation)
__device__ float g_q[(size_t)B_*H_*T_*D_];
__device__ float g_k[(size_t)B_*H_*T_*D_];
__device__ float g_v[(size_t)B_*H_*T_*D_];
__device__ float g_ao[(size_t)M_*C_];

// ---------------------------------------------------------------------------
// tf32 helpers
// ---------------------------------------------------------------------------
__device__ __forceinline__ unsigned f2tf(float x) {
    unsigned r; asm("cvt.rna.tf32.f32 %0, %1;" : "=r"(r) : "f"(x)); return r;
}
__device__ __forceinline__ float f2tff(float x) { return __uint_as_float(f2tf(x)); }
__device__ __forceinline__ float4 cvt4(float4 v) {
    return make_float4(f2tff(v.x), f2tff(v.y), f2tff(v.z), f2tff(v.w));
}

__device__ __forceinline__ void mma_tf32(float* d,
    unsigned a0, unsigned a1, unsigned a2, unsigned a3, unsigned b0, unsigned b1)
{
    asm volatile(
        "mma.sync.aligned.m16n8k8.row.col.f32.tf32.tf32.f32 "
        "{%0,%1,%2,%3}, {%4,%5,%6,%7}, {%8,%9}, {%0,%1,%2,%3};\n"
        : "+f"(d[0]), "+f"(d[1]), "+f"(d[2]), "+f"(d[3])
        : "r"(a0), "r"(a1), "r"(a2), "r"(a3), "r"(b0), "r"(b1));
}

// ---------------------------------------------------------------------------
// GEMM mainloop: Y = A @ W^T, A [M,K] rm, W [N,K] rm. 128x128 tile, BK=16.
// 8 warps (2 m x 4 n), warp tile 64x32, m16n8k8 tf32 mma.
// Smem row-major [128][20]: bank = (20*row + k) & 31 is conflict-free for
// both the a0..a3 / b0..b1 fragment patterns (quad-row x quad-col).
// ---------------------------------------------------------------------------
__device__ __forceinline__ void gemm_tile(
    const float* __restrict__ Ab, const float* __restrict__ Wb,
    float (&acc)[4][4][4])
{
    __shared__ __align__(16) float As[128][20];
    __shared__ __align__(16) float Bs[128][20];

    const int tid = threadIdx.x;
    const int lane = tid & 31, w = tid >> 5;
    const int mw = w >> 2, nw = w & 3;
    const int r = lane >> 2, cq = lane & 3;

#pragma unroll
    for (int mt = 0; mt < 4; mt++)
#pragma unroll
        for (int nt = 0; nt < 4; nt++)
#pragma unroll
            for (int c = 0; c < 4; c++) acc[mt][nt][c] = 0.f;

    float4 pa[2], pb[2];
#pragma unroll
    for (int l = 0; l < 2; l++) {
        int idx = tid + l*256;
        pa[l] = *(const float4*)(Ab + (size_t)(idx>>2)*C_ + ((idx&3)<<2));
        pb[l] = *(const float4*)(Wb + (size_t)(idx>>2)*C_ + ((idx&3)<<2));
    }

    for (int k0 = 0; k0 < C_; k0 += 16) {
        __syncthreads();
#pragma unroll
        for (int l = 0; l < 2; l++) {
            int idx = tid + l*256;
            int row = idx>>2, kc = (idx&3)<<2;
            *(float4*)&As[row][kc] = cvt4(pa[l]);
            *(float4*)&Bs[row][kc] = cvt4(pb[l]);
        }
        __syncthreads();
        if (k0 + 16 < C_) {
#pragma unroll
            for (int l = 0; l < 2; l++) {
                int idx = tid + l*256;
                pa[l] = *(const float4*)(Ab + (size_t)(idx>>2)*C_ + k0 + 16 + ((idx&3)<<2));
                pb[l] = *(const float4*)(Wb + (size_t)(idx>>2)*C_ + k0 + 16 + ((idx&3)<<2));
            }
        }
#pragma unroll
        for (int ks = 0; ks < 16; ks += 8) {
            unsigned af[4][4];
#pragma unroll
            for (int mt = 0; mt < 4; mt++) {
                const float* p = &As[mw*64 + mt*16 + r][ks + cq];
                af[mt][0] = __float_as_uint(p[0]);
                af[mt][1] = __float_as_uint(p[8*20]);
                af[mt][2] = __float_as_uint(p[4]);
                af[mt][3] = __float_as_uint(p[8*20 + 4]);
            }
#pragma unroll
            for (int nt = 0; nt < 4; nt++) {
                const float* p = &Bs[nw*32 + nt*8 + r][ks + cq];
                unsigned b0 = __float_as_uint(p[0]);
                unsigned b1 = __float_as_uint(p[4]);
#pragma unroll
                for (int mt = 0; mt < 4; mt++)
                    mma_tf32(acc[mt][nt], af[mt][0], af[mt][1], af[mt][2], af[mt][3], b0, b1);
            }
        }
    }
}

__global__ __launch_bounds__(256) void gemm_qkv(
    const float* __restrict__ x,
    const float* __restrict__ wq,
    const float* __restrict__ wk,
    const float* __restrict__ wv)
{
    const float* W = (blockIdx.z == 0) ? wq : (blockIdx.z == 1) ? wk : wv;
    float* out     = (blockIdx.z == 0) ? g_q : (blockIdx.z == 1) ? g_k : g_v;
    const float scale = (blockIdx.z == 0) ? SCALE_ : 1.f;

    float acc[4][4][4];
    gemm_tile(x + (size_t)blockIdx.y*128*C_, W + (size_t)blockIdx.x*128*C_, acc);

    const int lane = threadIdx.x & 31, w = threadIdx.x >> 5;
    const int mw = w >> 2, nw = w & 3;
    const int r = lane >> 2, cq = lane & 3;

#pragma unroll
    for (int mt = 0; mt < 4; mt++)
#pragma unroll
        for (int hh = 0; hh < 2; hh++) {
            int m = blockIdx.y*128 + mw*64 + mt*16 + r + 8*hh;
            int b = m >> 11, t = m & (T_-1);
#pragma unroll
            for (int nt = 0; nt < 4; nt++) {
                int n = blockIdx.x*128 + nw*32 + nt*8 + 2*cq;
                int h = n >> 6, d = n & 63;
                float2 v = make_float2(acc[mt][nt][2*hh]*scale, acc[mt][nt][2*hh+1]*scale);
                *(float2*)&out[(((size_t)(b*H_ + h))*T_ + t)*D_ + d] = v;
            }
        }
}

__global__ __launch_bounds__(256) void gemm_out(
    const float* __restrict__ wo,
    float* __restrict__ out)
{
    float acc[4][4][4];
    gemm_tile(g_ao + (size_t)blockIdx.y*128*C_, wo + (size_t)blockIdx.x*128*C_, acc);

    const int lane = threadIdx.x & 31, w = threadIdx.x >> 5;
    const int mw = w >> 2, nw = w & 3;
    const int r = lane >> 2, cq = lane & 3;

#pragma unroll
    for (int mt = 0; mt < 4; mt++)
#pragma unroll
        for (int hh = 0; hh < 2; hh++) {
            int m = blockIdx.y*128 + mw*64 + mt*16 + r + 8*hh;
#pragma unroll
            for (int nt = 0; nt < 4; nt++) {
                int n = blockIdx.x*128 + nw*32 + nt*8 + 2*cq;
                float2 v = make_float2(acc[mt][nt][2*hh], acc[mt][nt][2*hh+1]);
                *(float2*)&out[(size_t)m*C_ + n] = v;
            }
        }
}

// ---------------------------------------------------------------------------
// Flash attention with tf32 mma. Block = 256 thr (8 warps: 4 q-groups x 2
// n-halves). Per (bh, 128-q tile). Causal, online softmax.
// Smem strides chosen so all fragment LDS patterns are bank-conflict-free.
// ---------------------------------------------------------------------------
#define PQ 68
#define PV 72
#define PP 132
#define OFF_Q  0
#define OFF_K  (128*PQ)
#define OFF_V  (OFF_K + 128*PQ)
#define OFF_P  (OFF_V + 128*PV)
#define OFF_RM (OFF_P + 128*PP)
#define OFF_RS (OFF_RM + 256)
#define ATT_SMEM ((OFF_RS + 256) * 4)

__global__ void __launch_bounds__(256, 1) attn_kernel()
{
    extern __shared__ float sm[];
    float* Qs = sm + OFF_Q;
    float* Ks = sm + OFF_K;
    float* Vs = sm + OFF_V;
    float* Ps = sm + OFF_P;
    float* RM = sm + OFF_RM;   // [2][128] partial row max
    float* RS = sm + OFF_RS;   // [2][128] partial row sum

    const int tid = threadIdx.x, lane = tid & 31, w = tid >> 5;
    const int mw = w & 3, nw = w >> 2;
    const int r = lane >> 2, cq = lane & 3;
    const int bh = blockIdx.y;
    const int qt = 15 - (int)blockIdx.x;   // heavy tiles first

    const float* Qg = g_q + ((size_t)bh*T_ + (size_t)qt*128) * D_;
    const float* Kg = g_k + (size_t)bh*T_*D_;
    const float* Vg = g_v + (size_t)bh*T_*D_;

    // Load Q tile (already pre-scaled by SCALE in gemm_qkv epilogue)
#pragma unroll
    for (int l = 0; l < 8; l++) {
        int idx = tid + l*256;
        int tok = idx >> 4, d0 = (idx & 15) << 2;
        float4 v = *(const float4*)(Qg + (size_t)tok*D_ + d0);
        *(float4*)&Qs[tok*PQ + d0] = cvt4(v);
    }

    float o[2][4][4];
    float mI[2][2], lI[2][2];
#pragma unroll
    for (int mt = 0; mt < 2; mt++) {
        mI[mt][0] = -INFINITY; mI[mt][1] = -INFINITY;
        lI[mt][0] = 0.f;       lI[mt][1] = 0.f;
#pragma unroll
        for (int nt = 0; nt < 4; nt++)
#pragma unroll
            for (int c = 0; c < 4; c++) o[mt][nt][c] = 0.f;
    }

    for (int kt = 0; kt <= qt; kt++) {
        __syncthreads();   // prev PV done with Ks/Vs/Ps
#pragma unroll
        for (int l = 0; l < 8; l++) {
            int idx = tid + l*256;
            int tok = idx >> 4, d0 = (idx & 15) << 2;
            size_t g = ((size_t)(kt*128 + tok))*D_ + d0;
            *(float4*)&Ks[tok*PQ + d0] = cvt4(*(const float4*)(Kg + g));
            *(float4*)&Vs[tok*PV + d0] = cvt4(*(const float4*)(Vg + g));
        }
        __syncthreads();

        // ---- S = Q K^T : warp covers rows [32mw,32mw+32), cols [64nw,64nw+64)
        float sacc[2][8][4];
#pragma unroll
        for (int mt = 0; mt < 2; mt++)
#pragma unroll
            for (int nt = 0; nt < 8; nt++)
#pragma unroll
                for (int c = 0; c < 4; c++) sacc[mt][nt][c] = 0.f;

#pragma unroll 2
        for (int ks = 0; ks < 8; ks++) {
            unsigned aq[2][4];
#pragma unroll
            for (int mt = 0; mt < 2; mt++) {
                const float* p = &Qs[(mw*32 + mt*16 + r)*PQ + ks*8 + cq];
                aq[mt][0] = __float_as_uint(p[0]);
                aq[mt][1] = __float_as_uint(p[8*PQ]);
                aq[mt][2] = __float_as_uint(p[4]);
                aq[mt][3] = __float_as_uint(p[8*PQ + 4]);
            }
#pragma unroll
            for (int nt = 0; nt < 8; nt++) {
                const float* p = &Ks[(nw*64 + nt*8 + r)*PQ + ks*8 + cq];
                unsigned b0 = __float_as_uint(p[0]);
                unsigned b1 = __float_as_uint(p[4]);
                mma_tf32(sacc[0][nt], aq[0][0], aq[0][1], aq[0][2], aq[0][3], b0, b1);
                mma_tf32(sacc[1][nt], aq[1][0], aq[1][1], aq[1][2], aq[1][3], b0, b1);
            }
        }

        if (kt == qt) {   // causal mask on diagonal tile
#pragma unroll
            for (int mt = 0; mt < 2; mt++)
#pragma unroll
                for (int nt = 0; nt < 8; nt++)
#pragma unroll
                    for (int c = 0; c < 4; c++) {
                        int row = mw*32 + mt*16 + r + 8*(c>>1);
                        int col = nw*64 + nt*8 + 2*cq + (c&1);
                        if (col > row) sacc[mt][nt][c] = -INFINITY;
                    }
        }

        // ---- partial row max (per warp), then cross-warp combine via smem
        float mx[2][2];
#pragma unroll
        for (int mt = 0; mt < 2; mt++) {
            float m0 = -INFINITY, m1 = -INFINITY;
#pragma unroll
            for (int nt = 0; nt < 8; nt++) {
                m0 = fmaxf(m0, fmaxf(sacc[mt][nt][0], sacc[mt][nt][1]));
                m1 = fmaxf(m1, fmaxf(sacc[mt][nt][2], sacc[mt][nt][3]));
            }
            m0 = fmaxf(m0, __shfl_xor_sync(0xffffffffu, m0, 1));
            m0 = fmaxf(m0, __shfl_xor_sync(0xffffffffu, m0, 2));
            m1 = fmaxf(m1, __shfl_xor_sync(0xffffffffu, m1, 1));
            m1 = fmaxf(m1, __shfl_xor_sync(0xffffffffu, m1, 2));
            mx[mt][0] = m0; mx[mt][1] = m1;
        }
        if (cq == 0) {
#pragma unroll
            for (int mt = 0; mt < 2; mt++) {
                RM[nw*128 + mw*32 + mt*16 + r]     = mx[mt][0];
                RM[nw*128 + mw*32 + mt*16 + r + 8] = mx[mt][1];
            }
        }
        __syncthreads();

        float corr[2][2];
#pragma unroll
        for (int mt = 0; mt < 2; mt++)
#pragma unroll
            for (int h = 0; h < 2; h++) {
                int row = mw*32 + mt*16 + r + 8*h;
                float mtile = fmaxf(RM[row], RM[128 + row]);
                float mn = fmaxf(mI[mt][h], mtile);
                corr[mt][h] = __expf(mI[mt][h] - mn);
                mI[mt][h] = mn;
            }

        // ---- exp, row sums, store P (tf32-rounded) to smem
        float sum[2][2] = {{0.f,0.f},{0.f,0.f}};
#pragma unroll
        for (int mt = 0; mt < 2; mt++) {
            int rowb = mw*32 + mt*16 + r;
#pragma unroll
            for (int nt = 0; nt < 8; nt++) {
                float p0 = __expf(sacc[mt][nt][0] - mI[mt][0]);
                float p1 = __expf(sacc[mt][nt][1] - mI[mt][0]);
                float p2 = __expf(sacc[mt][nt][2] - mI[mt][1]);
                float p3 = __expf(sacc[mt][nt][3] - mI[mt][1]);
                sum[mt][0] += p0 + p1;
                sum[mt][1] += p2 + p3;
                int col = nw*64 + nt*8 + 2*cq;
                *(float2*)&Ps[rowb*PP + col]     = make_float2(f2tff(p0), f2tff(p1));
                *(float2*)&Ps[(rowb+8)*PP + col] = make_float2(f2tff(p2), f2tff(p3));
            }
        }
#pragma unroll
        for (int mt = 0; mt < 2; mt++)
#pragma unroll
            for (int h = 0; h < 2; h++) {
                sum[mt][h] += __shfl_xor_sync(0xffffffffu, sum[mt][h], 1);
                sum[mt][h] += __shfl_xor_sync(0xffffffffu, sum[mt][h], 2);
            }
        if (cq == 0) {
#pragma unroll
            for (int mt = 0; mt < 2; mt++) {
                RS[nw*128 + mw*32 + mt*16 + r]     = sum[mt][0];
                RS[nw*128 + mw*32 + mt*16 + r + 8] = sum[mt][1];
            }
        }
        // rescale O by corr
#pragma unroll
        for (int mt = 0; mt < 2; mt++)
#pragma unroll
            for (int nt = 0; nt < 4; nt++) {
                o[mt][nt][0] *= corr[mt][0];
                o[mt][nt][1] *= corr[mt][0];
                o[mt][nt][2] *= corr[mt][1];
                o[mt][nt][3] *= corr[mt][1];
            }
        __syncthreads();
#pragma unroll
        for (int mt = 0; mt < 2; mt++)
#pragma unroll
            for (int h = 0; h < 2; h++) {
                int row = mw*32 + mt*16 + r + 8*h;
                lI[mt][h] = lI[mt][h]*corr[mt][h] + RS[row] + RS[128 + row];
            }

        // ---- O += P V : warp covers rows [32mw,+32), d-cols [32nw,+32)
#pragma unroll 4
        for (int ks = 0; ks < 16; ks++) {
            unsigned ap[2][4];
#pragma unroll
            for (int mt = 0; mt < 2; mt++) {
                const float* p = &Ps[(mw*32 + mt*16 + r)*PP + ks*8 + cq];
                ap[mt][0] = __float_as_uint(p[0]);
                ap[mt][1] = __float_as_uint(p[8*PP]);
                ap[mt][2] = __float_as_uint(p[4]);
                ap[mt][3] = __float_as_uint(p[8*PP + 4]);
            }
#pragma unroll
            for (int nt = 0; nt < 4; nt++) {
                const float* p = &Vs[(ks*8 + cq)*PV + nw*32 + nt*8 + r];
                unsigned b0 = __float_as_uint(p[0]);
                unsigned b1 = __float_as_uint(p[4*PV]);
                mma_tf32(o[0][nt], ap[0][0], ap[0][1], ap[0][2], ap[0][3], b0, b1);
                mma_tf32(o[1][nt], ap[1][0], ap[1][1], ap[1][2], ap[1][3], b0, b1);
            }
        }
    }

    // ---- normalize + write to g_ao [B,T,C]
    const int b = bh >> 4, h = bh & 15;
#pragma unroll
    for (int mt = 0; mt < 2; mt++)
#pragma unroll
        for (int hh = 0; hh < 2; hh++) {
            int row = mw*32 + mt*16 + r + 8*hh;
            int t = qt*128 + row;
            float inv = 1.f / lI[mt][hh];
#pragma unroll
            for (int nt = 0; nt < 4; nt++) {
                int d = nw*32 + nt*8 + 2*cq;
                float2 v = make_float2(o[mt][nt][2*hh]*inv, o[mt][nt][2*hh+1]*inv);
                *(float2*)&g_ao[((size_t)(b*T_ + t))*C_ + h*64 + d] = v;
            }
        }
}

// ---------------------------------------------------------------------------

extern "C" void kernel_launch(void* const* d_in, const int* in_sizes, int n_in,
                              void* d_out, int out_size)
{
    const float* x  = (const float*)d_in[0];
    // d_in[1] = causal mask (deterministic; applied analytically)
    const float* wq = (const float*)d_in[2];
    const float* wk = (const float*)d_in[3];
    const float* wv = (const float*)d_in[4];
    const float* wo = (const float*)d_in[5];
    float* out = (float*)d_out;

    gemm_qkv<<<dim3(C_/128, M_/128, 3), 256>>>(x, wq, wk, wv);

    cudaFuncSetAttribute(attn_kernel, cudaFuncAttributeMaxDynamicSharedMemorySize, ATT_SMEM);
    attn_kernel<<<dim3(16, B_*H_), 256, ATT_SMEM>>>();

    gemm_out<<<dim3(C_/128, M_/128), 256>>>(wo, out);
}